// round 6
// baseline (speedup 1.0000x reference)
#include <cuda_runtime.h>
#include <cstdint>

#define NFEAT 784
#define NCLS  10
#define KC    16
#define KSPLIT 400                   // warps 0-6: k<400 (25 tiles); 7-13: k>=400 (24)
#define TPB   448                    // 14 warps
#define NWARP 14
#define HWARP 7
#define RPT   2
#define ROWSPW 64                    // rows per warp-pair
#define ROWSPC (HWARP * ROWSPW)      // 448 rows per CTA -> grid 147
#define XSTR  20                     // 16 + 4 pad: conflict-free LDS.128
#define NBUF  2                      // warp-private ring depth
#define RINGF (NBUF * ROWSPW * XSTR)               // 2560 floats per warp
#define XS_FLOATS (NWARP * RINGF)                  // 35840
#define AS_FLOATS (NCLS * NFEAT)                   // 7840
#define RED_FLOATS (NWARP * NCLS)                  // 140
#define SMEM_FLOATS (XS_FLOATS + AS_FLOATS + RED_FLOATS + 2)
#define SMEM_BYTES  (SMEM_FLOATS * 4)              // ~171.2 KB -> 1 CTA/SM

// ---------------------------------------------------------------------------
__device__ __forceinline__ void cp_async16(uint32_t saddr, const void* gptr) {
    asm volatile("cp.async.cg.shared.global [%0], [%1], 16;\n"
                 :: "r"(saddr), "l"(gptr));
}
#define CP_COMMIT() asm volatile("cp.async.commit_group;\n" ::: "memory")
#define CP_WAIT(n)  asm volatile("cp.async.wait_group %0;\n" :: "n"(n) : "memory")
#define FMA_F32X2(d, a, b) \
    asm volatile("fma.rn.f32x2 %0, %1, %2, %0;" : "+l"(d) : "l"(a), "l"(b))

extern __shared__ float smem[];

// Warp-private stage of one tile: this warp's 64 rows x 16 k, 8 chunks/lane.
__device__ __forceinline__ void issue_tile(const float* __restrict__ x,
                                           float* xw, int wrow0, int Brows,
                                           int lane, int t, int kbase) {
    const int k0 = kbase + t * KC;
    float* xb = xw + (t & (NBUF - 1)) * ROWSPW * XSTR;
#pragma unroll
    for (int i = 0; i < 8; ++i) {
        int g  = lane + i * 32;        // 0..255: (row, 16B-chunk)
        int r  = g >> 2;
        int ch = g & 3;
        int row = wrow0 + r;
        if (row >= Brows) row = Brows - 1;   // clamp (reads discarded)
        const float* gp = x + (size_t)row * NFEAT + k0 + ch * 4;
        uint32_t sa = (uint32_t)__cvta_generic_to_shared(xb + r * XSTR + ch * 4);
        cp_async16(sa, gp);
    }
    CP_COMMIT();
}

// ---------------------------------------------------------------------------
// Split-K fused kernel: per-CTA fold of sparse+FC into A[10,784] (shared),
// then each row-group is owned by a PAIR of warps (w, w+7) covering disjoint
// K ranges, each with a private 2-deep cp.async ring. Barrier-free mainloop,
// one smem reduction at the end. 14 warps/SM, 2 rows/thread, f32x2 FMA.
// ---------------------------------------------------------------------------
__global__ void __launch_bounds__(TPB, 1)
fused_kernel(const float* __restrict__ x,
             const float* __restrict__ W,
             const float* __restrict__ Bsp,
             const float* __restrict__ fcw,
             const float* __restrict__ fcb,
             float* __restrict__ out, int Brows)
{
    float* As  = smem + XS_FLOATS;            // [10][784]
    float* red = As + AS_FLOATS;              // [14][10]

    const int tid  = threadIdx.x;
    const int wid  = tid >> 5;
    const int lane = tid & 31;
    const int wpair = (wid < HWARP) ? wid : wid - HWARP;   // row-group id
    const int half  = (wid < HWARP) ? 0 : 1;               // K-half
    const int kbase = half ? KSPLIT : 0;
    const int ntw   = half ? (NFEAT - KSPLIT) / KC : KSPLIT / KC;  // 24 / 25
    const int wrow0 = blockIdx.x * ROWSPC + wpair * ROWSPW;
    float* xw = smem + wid * RINGF;

    // Kick DRAM immediately: 2 tiles in flight per warp while A is built.
    issue_tile(x, xw, wrow0, Brows, lane, 0, kbase);
    issue_tile(x, xw, wrow0, Brows, lane, 1, kbase);

    // ---- build A and per-warp bias partials in shared ----
    float part[NCLS];
#pragma unroll
    for (int c = 0; c < NCLS; ++c) part[c] = 0.f;

    for (int k = tid; k < NFEAT; k += TPB) {
        // scatter column map (faithful to the reference's i=782 wraparound bug)
        int c0i = (k == NFEAT - 2) ? 0 : k;
        int c1i = (k == NFEAT - 2) ? 1 : ((k + 1 == NFEAT) ? 0 : k + 1);
        float w0 = W[2*k],   w1 = W[2*k+1];
        float b0 = Bsp[2*k], b1 = Bsp[2*k+1];
#pragma unroll
        for (int c = 0; c < NCLS; ++c) {
            float f0 = __ldg(fcw + c * NFEAT + c0i);
            float f1 = __ldg(fcw + c * NFEAT + c1i);
            As[c * NFEAT + k] = f0 * w0 + f1 * w1;
            part[c] += f0 * b0 + f1 * b1;
        }
    }
#pragma unroll
    for (int off = 16; off; off >>= 1)
#pragma unroll
        for (int c = 0; c < NCLS; ++c)
            part[c] += __shfl_down_sync(0xffffffffu, part[c], off);
    if (lane == 0)
#pragma unroll
        for (int c = 0; c < NCLS; ++c) red[wid * NCLS + c] = part[c];
    __syncthreads();     // A + red visible; mainloop is barrier-free

    // ---- barrier-free main GEMV loop over this warp's K-half ----
    unsigned long long acc0[NCLS], acc1[NCLS];
#pragma unroll
    for (int c = 0; c < NCLS; ++c) { acc0[c] = 0ULL; acc1[c] = 0ULL; }

    const float* Aptr = As + kbase;
    for (int t = 0; t < ntw; ++t) {
        if (t == ntw - 1) { CP_WAIT(0); } else { CP_WAIT(1); }

        const float* xb  = xw + (t & (NBUF - 1)) * ROWSPW * XSTR;
        const float* xr0 = xb + lane * XSTR;
        const float* xr1 = xb + (32 + lane) * XSTR;
#pragma unroll
        for (int kc = 0; kc < 4; ++kc) {
            ulonglong2 v0 = *(const ulonglong2*)(xr0 + kc * 4);
            ulonglong2 v1 = *(const ulonglong2*)(xr1 + kc * 4);
#pragma unroll
            for (int c = 0; c < NCLS; ++c) {
                ulonglong2 av = *(const ulonglong2*)(Aptr + c * NFEAT + kc * 4);
                FMA_F32X2(acc0[c], v0.x, av.x);
                FMA_F32X2(acc0[c], v0.y, av.y);
                FMA_F32X2(acc1[c], v1.x, av.x);
                FMA_F32X2(acc1[c], v1.y, av.y);
            }
        }
        Aptr += KC;
        if (t + 2 < ntw) issue_tile(x, xw, wrow0, Brows, lane, t + 2, kbase);
    }

    // ---- cross-warp K reduction through (now dead) ring smem ----
    if (half) {
        unsigned long long* sc = (unsigned long long*)xw;   // own ring, dead
#pragma unroll
        for (int c = 0; c < NCLS; ++c) {
            sc[lane + 32 * c]            = acc0[c];
            sc[lane + 32 * (NCLS + c)]   = acc1[c];
        }
    }
    __syncthreads();
    if (half) return;    // upper warps done

    const unsigned long long* sc =
        (const unsigned long long*)(smem + (wid + HWARP) * RINGF);

    float c0v[NCLS];
#pragma unroll
    for (int c = 0; c < NCLS; ++c) {
        float s = __ldg(fcb + c);
#pragma unroll
        for (int w = 0; w < NWARP; ++w) s += red[w * NCLS + c];
        c0v[c] = s;
    }

#pragma unroll
    for (int rsel = 0; rsel < RPT; ++rsel) {
        float logit[NCLS];
#pragma unroll
        for (int c = 0; c < NCLS; ++c) {
            unsigned long long a = rsel ? acc1[c] : acc0[c];
            unsigned long long b = sc[lane + 32 * (rsel * NCLS + c)];
            float lo = __uint_as_float((unsigned)(a & 0xffffffffu))
                     + __uint_as_float((unsigned)(b & 0xffffffffu));
            float hi = __uint_as_float((unsigned)(a >> 32))
                     + __uint_as_float((unsigned)(b >> 32));
            logit[c] = lo + hi + c0v[c];
        }
        float m = logit[0];
#pragma unroll
        for (int c = 1; c < NCLS; ++c) m = fmaxf(m, logit[c]);
        float ssum = 0.f;
#pragma unroll
        for (int c = 0; c < NCLS; ++c) { logit[c] = __expf(logit[c] - m); ssum += logit[c]; }
        float inv = 1.0f / ssum;

        const int row = wrow0 + lane + rsel * 32;
        if (row < Brows) {
            float2* po = (float2*)(out + (size_t)row * NCLS);
#pragma unroll
            for (int c = 0; c < NCLS; c += 2)
                po[c >> 1] = make_float2(logit[c] * inv, logit[c + 1] * inv);
        }
    }
}

// ---------------------------------------------------------------------------
extern "C" void kernel_launch(void* const* d_in, const int* in_sizes, int n_in,
                              void* d_out, int out_size) {
    const float* x   = (const float*)d_in[0];
    const float* W   = (const float*)d_in[1];
    const float* bsp = (const float*)d_in[2];
    const float* fcw = (const float*)d_in[3];
    const float* fcb = (const float*)d_in[4];
    float* out = (float*)d_out;
    const int Brows = in_sizes[0] / NFEAT;

    cudaFuncSetAttribute(fused_kernel,
                         cudaFuncAttributeMaxDynamicSharedMemorySize, SMEM_BYTES);

    const int grid = (Brows + ROWSPC - 1) / ROWSPC;   // 147 for B=65536
    fused_kernel<<<grid, TPB, SMEM_BYTES>>>(x, W, bsp, fcw, fcb, out, Brows);
}

// round 7
// speedup vs baseline: 1.0931x; 1.0931x over previous
#include <cuda_runtime.h>
#include <cstdint>

#define NFEAT 784
#define NCLS  10
#define KC    16
#define KSPLIT 400                   // warps 0-6: k<400 (25 tiles); 7-13: k>=400 (24)
#define TPB   448                    // 14 warps
#define NWARP 14
#define HWARP 7
#define RPT   2
#define ROWSPW 64                    // rows per warp-pair
#define ROWSPC (HWARP * ROWSPW)      // 448 rows per CTA -> grid 147
#define XSTR  16                     // no pad; conflicts avoided via chunk swizzle
#define NBUF  3                      // warp-private ring depth (restored)
#define RINGF (NBUF * ROWSPW * XSTR)               // 3072 floats per warp
#define XS_FLOATS (NWARP * RINGF)                  // 43008
#define AS_FLOATS (NCLS * NFEAT)                   // 7840
#define RED_FLOATS (NWARP * NCLS)                  // 140
#define SMEM_FLOATS (XS_FLOATS + AS_FLOATS + RED_FLOATS + 2)
#define SMEM_BYTES  (SMEM_FLOATS * 4)              // ~204 KB -> 1 CTA/SM

// ---------------------------------------------------------------------------
__device__ __forceinline__ void cp_async16(uint32_t saddr, const void* gptr) {
    asm volatile("cp.async.cg.shared.global [%0], [%1], 16;\n"
                 :: "r"(saddr), "l"(gptr));
}
#define CP_COMMIT() asm volatile("cp.async.commit_group;\n" ::: "memory")
#define CP_WAIT(n)  asm volatile("cp.async.wait_group %0;\n" :: "n"(n) : "memory")
#define FMA_F32X2(d, a, b) \
    asm volatile("fma.rn.f32x2 %0, %1, %2, %0;" : "+l"(d) : "l"(a), "l"(b))

extern __shared__ float smem[];

// Warp-private stage of one tile. Chunk ch of row r lands at swizzled
// position (ch + (r>>1)) & 3 within the row's 64B -> conflict-free reads.
__device__ __forceinline__ void issue_tile(const float* __restrict__ x,
                                           float* xw, int wrow0, int Brows,
                                           int lane, int t, int kbase) {
    const int k0 = kbase + t * KC;
    float* xb = xw + (t % NBUF) * ROWSPW * XSTR;
#pragma unroll
    for (int i = 0; i < 8; ++i) {
        int g  = lane + i * 32;        // 0..255: (row, 16B-chunk)
        int r  = g >> 2;
        int ch = g & 3;
        int row = wrow0 + r;
        if (row >= Brows) row = Brows - 1;   // clamp (reads discarded)
        const float* gp = x + (size_t)row * NFEAT + k0 + ch * 4;
        int p = (ch + (r >> 1)) & 3;         // swizzled chunk position
        uint32_t sa = (uint32_t)__cvta_generic_to_shared(xb + r * XSTR + p * 4);
        cp_async16(sa, gp);
    }
    CP_COMMIT();
}

// ---------------------------------------------------------------------------
// Split-K fused kernel, deep rings: warp pair (w, w+7) covers disjoint K
// ranges of the same 64 rows; each warp has a private 3-deep cp.async ring
// (wait distance 2). Barrier-free mainloop, one smem reduction at the end.
// ---------------------------------------------------------------------------
__global__ void __launch_bounds__(TPB, 1)
fused_kernel(const float* __restrict__ x,
             const float* __restrict__ W,
             const float* __restrict__ Bsp,
             const float* __restrict__ fcw,
             const float* __restrict__ fcb,
             float* __restrict__ out, int Brows)
{
    float* As  = smem + XS_FLOATS;            // [10][784]
    float* red = As + AS_FLOATS;              // [14][10]

    const int tid  = threadIdx.x;
    const int wid  = tid >> 5;
    const int lane = tid & 31;
    const int wpair = (wid < HWARP) ? wid : wid - HWARP;   // row-group id
    const int half  = (wid < HWARP) ? 0 : 1;               // K-half
    const int kbase = half ? KSPLIT : 0;
    const int ntw   = half ? (NFEAT - KSPLIT) / KC : KSPLIT / KC;  // 24 / 25
    const int wrow0 = blockIdx.x * ROWSPC + wpair * ROWSPW;
    float* xw = smem + wid * RINGF;

    // Per-thread swizzled read offsets (same for both row-sets: +32 rows = +16 ≡ 0 mod 4)
    const int sw = (lane >> 1) & 3;
    int off[4];
#pragma unroll
    for (int kc = 0; kc < 4; ++kc) off[kc] = ((kc + sw) & 3) * 4;

    // Kick DRAM: 3 tiles in flight per warp while A is built.
    issue_tile(x, xw, wrow0, Brows, lane, 0, kbase);
    issue_tile(x, xw, wrow0, Brows, lane, 1, kbase);
    issue_tile(x, xw, wrow0, Brows, lane, 2, kbase);

    // ---- build A and per-warp bias partials in shared ----
    float part[NCLS];
#pragma unroll
    for (int c = 0; c < NCLS; ++c) part[c] = 0.f;

    for (int k = tid; k < NFEAT; k += TPB) {
        // scatter column map (faithful to the reference's i=782 wraparound bug)
        int c0i = (k == NFEAT - 2) ? 0 : k;
        int c1i = (k == NFEAT - 2) ? 1 : ((k + 1 == NFEAT) ? 0 : k + 1);
        float w0 = W[2*k],   w1 = W[2*k+1];
        float b0 = Bsp[2*k], b1 = Bsp[2*k+1];
#pragma unroll
        for (int c = 0; c < NCLS; ++c) {
            float f0 = __ldg(fcw + c * NFEAT + c0i);
            float f1 = __ldg(fcw + c * NFEAT + c1i);
            As[c * NFEAT + k] = f0 * w0 + f1 * w1;
            part[c] += f0 * b0 + f1 * b1;
        }
    }
#pragma unroll
    for (int offr = 16; offr; offr >>= 1)
#pragma unroll
        for (int c = 0; c < NCLS; ++c)
            part[c] += __shfl_down_sync(0xffffffffu, part[c], offr);
    if (lane == 0)
#pragma unroll
        for (int c = 0; c < NCLS; ++c) red[wid * NCLS + c] = part[c];
    __syncthreads();     // A + red visible; mainloop is barrier-free

    // ---- barrier-free main GEMV loop over this warp's K-half ----
    unsigned long long acc0[NCLS], acc1[NCLS];
#pragma unroll
    for (int c = 0; c < NCLS; ++c) { acc0[c] = 0ULL; acc1[c] = 0ULL; }

    const float* Aptr = As + kbase;
    for (int t = 0; t < ntw; ++t) {
        if (t < ntw - 2)       { CP_WAIT(2); }
        else if (t == ntw - 2) { CP_WAIT(1); }
        else                   { CP_WAIT(0); }

        const float* xb  = xw + (t % NBUF) * ROWSPW * XSTR;
        const float* xr0 = xb + lane * XSTR;
        const float* xr1 = xb + (32 + lane) * XSTR;
#pragma unroll
        for (int kc = 0; kc < 4; ++kc) {
            ulonglong2 v0 = *(const ulonglong2*)(xr0 + off[kc]);
            ulonglong2 v1 = *(const ulonglong2*)(xr1 + off[kc]);
#pragma unroll
            for (int c = 0; c < NCLS; ++c) {
                ulonglong2 av = *(const ulonglong2*)(Aptr + c * NFEAT + kc * 4);
                FMA_F32X2(acc0[c], v0.x, av.x);
                FMA_F32X2(acc0[c], v0.y, av.y);
                FMA_F32X2(acc1[c], v1.x, av.x);
                FMA_F32X2(acc1[c], v1.y, av.y);
            }
        }
        Aptr += KC;
        if (t + 3 < ntw) issue_tile(x, xw, wrow0, Brows, lane, t + 3, kbase);
    }

    // ---- cross-warp K reduction through (now dead) ring smem ----
    if (half) {
        unsigned long long* sc = (unsigned long long*)xw;   // own ring, dead
#pragma unroll
        for (int c = 0; c < NCLS; ++c) {
            sc[lane + 32 * c]            = acc0[c];
            sc[lane + 32 * (NCLS + c)]   = acc1[c];
        }
    }
    __syncthreads();
    if (half) return;    // upper warps done

    const unsigned long long* sc =
        (const unsigned long long*)(smem + (wid + HWARP) * RINGF);

    float c0v[NCLS];
#pragma unroll
    for (int c = 0; c < NCLS; ++c) {
        float s = __ldg(fcb + c);
#pragma unroll
        for (int w = 0; w < NWARP; ++w) s += red[w * NCLS + c];
        c0v[c] = s;
    }

#pragma unroll
    for (int rsel = 0; rsel < RPT; ++rsel) {
        float logit[NCLS];
#pragma unroll
        for (int c = 0; c < NCLS; ++c) {
            unsigned long long a = rsel ? acc1[c] : acc0[c];
            unsigned long long b = sc[lane + 32 * (rsel * NCLS + c)];
            float lo = __uint_as_float((unsigned)(a & 0xffffffffu))
                     + __uint_as_float((unsigned)(b & 0xffffffffu));
            float hi = __uint_as_float((unsigned)(a >> 32))
                     + __uint_as_float((unsigned)(b >> 32));
            logit[c] = lo + hi + c0v[c];
        }
        float m = logit[0];
#pragma unroll
        for (int c = 1; c < NCLS; ++c) m = fmaxf(m, logit[c]);
        float ssum = 0.f;
#pragma unroll
        for (int c = 0; c < NCLS; ++c) { logit[c] = __expf(logit[c] - m); ssum += logit[c]; }
        float inv = 1.0f / ssum;

        const int row = wrow0 + lane + rsel * 32;
        if (row < Brows) {
            float2* po = (float2*)(out + (size_t)row * NCLS);
#pragma unroll
            for (int c = 0; c < NCLS; c += 2)
                po[c >> 1] = make_float2(logit[c] * inv, logit[c + 1] * inv);
        }
    }
}

// ---------------------------------------------------------------------------
extern "C" void kernel_launch(void* const* d_in, const int* in_sizes, int n_in,
                              void* d_out, int out_size) {
    const float* x   = (const float*)d_in[0];
    const float* W   = (const float*)d_in[1];
    const float* bsp = (const float*)d_in[2];
    const float* fcw = (const float*)d_in[3];
    const float* fcb = (const float*)d_in[4];
    float* out = (float*)d_out;
    const int Brows = in_sizes[0] / NFEAT;

    cudaFuncSetAttribute(fused_kernel,
                         cudaFuncAttributeMaxDynamicSharedMemorySize, SMEM_BYTES);

    const int grid = (Brows + ROWSPC - 1) / ROWSPC;   // 147 for B=65536
    fused_kernel<<<grid, TPB, SMEM_BYTES>>>(x, W, bsp, fcw, fcb, out, Brows);
}

// round 8
// speedup vs baseline: 1.1314x; 1.0350x over previous
#include <cuda_runtime.h>
#include <cstdint>

#define NFEAT 784
#define NCLS  10
#define KC    16
#define NT    49                     // 784 / 16
#define TPB   224                    // 7 warps
#define NWARP 7
#define RPT   2
#define ROWSPW 64                    // rows per warp
#define ROWSPC (NWARP * ROWSPW)      // 448 rows per CTA -> grid 147
#define XSTR  20                     // 16 + 4 pad: conflict-free LDS.128
#define NBUF  5                      // warp-private ring depth (R5+1)
#define RINGF (NBUF * ROWSPW * XSTR)               // 6400 floats per warp
#define XS_FLOATS (NWARP * RINGF)                  // 44800
#define AS_FLOATS (NCLS * NFEAT)                   // 7840
#define RED_FLOATS (NWARP * NCLS)                  // 70
#define SMEM_FLOATS (XS_FLOATS + AS_FLOATS + RED_FLOATS + 2)
#define SMEM_BYTES  (SMEM_FLOATS * 4)              // ~210.9 KB -> 1 CTA/SM

// ---------------------------------------------------------------------------
__device__ __forceinline__ void cp_async16(uint32_t saddr, const void* gptr) {
    asm volatile("cp.async.cg.shared.global [%0], [%1], 16;\n"
                 :: "r"(saddr), "l"(gptr));
}
#define CP_COMMIT() asm volatile("cp.async.commit_group;\n" ::: "memory")
#define CP_WAIT(n)  asm volatile("cp.async.wait_group %0;\n" :: "n"(n) : "memory")
#define FMA_F32X2(d, a, b) \
    asm volatile("fma.rn.f32x2 %0, %1, %2, %0;" : "+l"(d) : "l"(a), "l"(b))

extern __shared__ float smem[];

// Warp-private stage of tile t into ring slot `buf`: 64 rows x 16 k,
// 8 chunks/lane, one cp.async group. No CTA-level synchronization, ever.
__device__ __forceinline__ void issue_tile(const float* __restrict__ x,
                                           float* xw, int wrow0, int Brows,
                                           int lane, int t, int buf) {
    const int k0 = t * KC;
    float* xb = xw + buf * (ROWSPW * XSTR);
#pragma unroll
    for (int i = 0; i < 8; ++i) {
        int g  = lane + i * 32;        // 0..255: (row, 16B-chunk)
        int r  = g >> 2;
        int ch = g & 3;
        int row = wrow0 + r;
        if (row >= Brows) row = Brows - 1;   // clamp (reads discarded)
        const float* gp = x + (size_t)row * NFEAT + k0 + ch * 4;
        uint32_t sa = (uint32_t)__cvta_generic_to_shared(xb + r * XSTR + ch * 4);
        cp_async16(sa, gp);
    }
    CP_COMMIT();
}

// ---------------------------------------------------------------------------
// Fused, barrier-free mainloop (R5 layout): per-CTA fold of sparse+FC into
// A[10,784] (shared broadcast), each warp independently streams its own 64
// rows through a private 5-deep cp.async ring (wait distance 3). 2 rows/
// thread, packed f32x2 FMA.
// ---------------------------------------------------------------------------
__global__ void __launch_bounds__(TPB, 1)
fused_kernel(const float* __restrict__ x,
             const float* __restrict__ W,
             const float* __restrict__ Bsp,
             const float* __restrict__ fcw,
             const float* __restrict__ fcb,
             float* __restrict__ out, int Brows)
{
    float* As  = smem + XS_FLOATS;            // [10][784]
    float* red = As + AS_FLOATS;              // [7][10]

    const int tid  = threadIdx.x;
    const int wid  = tid >> 5;
    const int lane = tid & 31;
    const int wrow0 = blockIdx.x * ROWSPC + wid * ROWSPW;
    float* xw = smem + wid * RINGF;

    // Kick DRAM immediately: 4 tiles in flight per warp while A is built.
    issue_tile(x, xw, wrow0, Brows, lane, 0, 0);
    issue_tile(x, xw, wrow0, Brows, lane, 1, 1);
    issue_tile(x, xw, wrow0, Brows, lane, 2, 2);
    issue_tile(x, xw, wrow0, Brows, lane, 3, 3);

    // ---- build A and per-warp bias partials in shared ----
    float part[NCLS];
#pragma unroll
    for (int c = 0; c < NCLS; ++c) part[c] = 0.f;

    for (int k = tid; k < NFEAT; k += TPB) {
        // scatter column map (faithful to the reference's i=782 wraparound bug)
        int c0i = (k == NFEAT - 2) ? 0 : k;
        int c1i = (k == NFEAT - 2) ? 1 : ((k + 1 == NFEAT) ? 0 : k + 1);
        float w0 = W[2*k],   w1 = W[2*k+1];
        float b0 = Bsp[2*k], b1 = Bsp[2*k+1];
#pragma unroll
        for (int c = 0; c < NCLS; ++c) {
            float f0 = __ldg(fcw + c * NFEAT + c0i);
            float f1 = __ldg(fcw + c * NFEAT + c1i);
            As[c * NFEAT + k] = f0 * w0 + f1 * w1;
            part[c] += f0 * b0 + f1 * b1;
        }
    }
#pragma unroll
    for (int off = 16; off; off >>= 1)
#pragma unroll
        for (int c = 0; c < NCLS; ++c)
            part[c] += __shfl_down_sync(0xffffffffu, part[c], off);
    if (lane == 0)
#pragma unroll
        for (int c = 0; c < NCLS; ++c) red[wid * NCLS + c] = part[c];
    __syncthreads();     // the ONLY barrier: A + red visible to all warps

    // ---- barrier-free main GEMV loop: 2 rows/thread ----
    unsigned long long acc0[NCLS], acc1[NCLS];
#pragma unroll
    for (int c = 0; c < NCLS; ++c) { acc0[c] = 0ULL; acc1[c] = 0ULL; }

    const float* Aptr = As;
    int bufc = 0;                              // ring slot of tile t
    for (int t = 0; t < NT; ++t) {
        if (t < NT - 3)       { CP_WAIT(3); }
        else if (t == NT - 3) { CP_WAIT(2); }
        else if (t == NT - 2) { CP_WAIT(1); }
        else                  { CP_WAIT(0); }

        const float* xb  = xw + bufc * (ROWSPW * XSTR);
        const float* xr0 = xb + lane * XSTR;
        const float* xr1 = xb + (32 + lane) * XSTR;
#pragma unroll
        for (int kc = 0; kc < 4; ++kc) {
            ulonglong2 v0 = *(const ulonglong2*)(xr0 + kc * 4);
            ulonglong2 v1 = *(const ulonglong2*)(xr1 + kc * 4);
#pragma unroll
            for (int c = 0; c < NCLS; ++c) {
                ulonglong2 av = *(const ulonglong2*)(Aptr + c * NFEAT + kc * 4);
                FMA_F32X2(acc0[c], v0.x, av.x);
                FMA_F32X2(acc0[c], v0.y, av.y);
                FMA_F32X2(acc1[c], v1.x, av.x);
                FMA_F32X2(acc1[c], v1.y, av.y);
            }
        }
        Aptr += KC;
        if (t + 4 < NT) {
            int ibuf = bufc ? bufc - 1 : NBUF - 1;   // == (t+4) % 5
            issue_tile(x, xw, wrow0, Brows, lane, t + 4, ibuf);
        }
        bufc = (bufc == NBUF - 1) ? 0 : bufc + 1;
    }

    // ---- epilogue: bias from red (broadcast reads), softmax, store ----
    float c0v[NCLS];
#pragma unroll
    for (int c = 0; c < NCLS; ++c) {
        float s = __ldg(fcb + c);
#pragma unroll
        for (int w = 0; w < NWARP; ++w) s += red[w * NCLS + c];
        c0v[c] = s;
    }

#pragma unroll
    for (int rsel = 0; rsel < RPT; ++rsel) {
        const unsigned long long* acc = rsel ? acc1 : acc0;
        float logit[NCLS];
#pragma unroll
        for (int c = 0; c < NCLS; ++c) {
            float lo = __uint_as_float((unsigned)(acc[c] & 0xffffffffu));
            float hi = __uint_as_float((unsigned)(acc[c] >> 32));
            logit[c] = lo + hi + c0v[c];
        }
        float m = logit[0];
#pragma unroll
        for (int c = 1; c < NCLS; ++c) m = fmaxf(m, logit[c]);
        float ssum = 0.f;
#pragma unroll
        for (int c = 0; c < NCLS; ++c) { logit[c] = __expf(logit[c] - m); ssum += logit[c]; }
        float inv = 1.0f / ssum;

        const int row = wrow0 + lane + rsel * 32;
        if (row < Brows) {
            float2* po = (float2*)(out + (size_t)row * NCLS);
#pragma unroll
            for (int c = 0; c < NCLS; c += 2)
                po[c >> 1] = make_float2(logit[c] * inv, logit[c + 1] * inv);
        }
    }
}

// ---------------------------------------------------------------------------
extern "C" void kernel_launch(void* const* d_in, const int* in_sizes, int n_in,
                              void* d_out, int out_size) {
    const float* x   = (const float*)d_in[0];
    const float* W   = (const float*)d_in[1];
    const float* bsp = (const float*)d_in[2];
    const float* fcw = (const float*)d_in[3];
    const float* fcb = (const float*)d_in[4];
    float* out = (float*)d_out;
    const int Brows = in_sizes[0] / NFEAT;

    cudaFuncSetAttribute(fused_kernel,
                         cudaFuncAttributeMaxDynamicSharedMemorySize, SMEM_BYTES);

    const int grid = (Brows + ROWSPC - 1) / ROWSPC;   // 147 for B=65536
    fused_kernel<<<grid, TPB, SMEM_BYTES>>>(x, W, bsp, fcw, fcb, out, Brows);
}